// round 15
// baseline (speedup 1.0000x reference)
#include <cuda_runtime.h>

#define LTOT   4096
#define NST    64
#define BSZ    64
#define NCHUNK 128
#define LC     32

typedef unsigned long long u64t;

// Scratch (__device__ globals — no allocation allowed).
// g_Y[t][row n][col]: col 0..63 = Xloc (batch cols), col 64..127 = Ploc.
__device__ float g_Y [LTOT * 64 * 128];     // 128 MB
__device__ float g_S [NCHUNK * 64 * 128];
__device__ float g_S2[NCHUNK * 64 * 128];

// ---------------- packed f32x2 helpers --------------------------------------
__device__ __forceinline__ u64t ffma2(u64t a, u64t b, u64t c) {
  u64t d;
  asm("fma.rn.f32x2 %0, %1, %2, %3;" : "=l"(d) : "l"(a), "l"(b), "l"(c));
  return d;
}
__device__ __forceinline__ u64t fmul2(u64t a, u64t b) {
  u64t d;
  asm("mul.rn.f32x2 %0, %1, %2;" : "=l"(d) : "l"(a), "l"(b));
  return d;
}
__device__ __forceinline__ u64t fdup(float v) {
  u64t d; unsigned r = __float_as_uint(v);
  asm("mov.b64 %0, {%1, %1};" : "=l"(d) : "r"(r));
  return d;
}

// AsD: duplicated-A SMEM, float2 (a,a) per entry, row stride 66 entries.
#define ASD_FLOATS (64 * 66 * 2)   // 8448 floats = 33792 B

// Store 8 consecutive k-values of one A row, duplicated.
__device__ __forceinline__ void store_dup8(float* AsD, int row, int k8,
                                           float4 a, float4 b) {
  float* p = &AsD[(row * 66 + k8) * 2];
  *reinterpret_cast<float4*>(p)      = make_float4(a.x, a.x, a.y, a.y);
  *reinterpret_cast<float4*>(p + 4)  = make_float4(a.z, a.z, a.w, a.w);
  *reinterpret_cast<float4*>(p + 8)  = make_float4(b.x, b.x, b.y, b.y);
  *reinterpret_cast<float4*>(p + 12) = make_float4(b.z, b.z, b.w, b.w);
}

// Packed GEMM fragment: acc[4][P] (f32x2), rows r0..r0+3, col pairs at c0.
// W = Ys row stride in floats. AsD holds duplicated A.
template<int W, int P>
__device__ __forceinline__ void gemmP(const float* __restrict__ AsD,
                                      const float* __restrict__ Ys,
                                      u64t acc[4][P], int r0, int c0) {
#pragma unroll 8
  for (int k = 0; k < 64; k += 2) {
    u64t a0[4], a1[4];
#pragma unroll
    for (int i = 0; i < 4; ++i) {
      float4 av = *reinterpret_cast<const float4*>(&AsD[((r0 + i) * 66 + k) * 2]);
      a0[i] = reinterpret_cast<const u64t*>(&av)[0];
      a1[i] = reinterpret_cast<const u64t*>(&av)[1];
    }
    u64t y0[P], y1[P];
    if constexpr (P == 2) {
      float4 v0 = *reinterpret_cast<const float4*>(&Ys[k * W + c0]);
      float4 v1 = *reinterpret_cast<const float4*>(&Ys[(k + 1) * W + c0]);
      y0[0] = reinterpret_cast<const u64t*>(&v0)[0];
      y0[1] = reinterpret_cast<const u64t*>(&v0)[1];
      y1[0] = reinterpret_cast<const u64t*>(&v1)[0];
      y1[1] = reinterpret_cast<const u64t*>(&v1)[1];
    } else {
      float2 v0 = *reinterpret_cast<const float2*>(&Ys[k * W + c0]);
      float2 v1 = *reinterpret_cast<const float2*>(&Ys[(k + 1) * W + c0]);
      y0[0] = *reinterpret_cast<const u64t*>(&v0);
      y1[0] = *reinterpret_cast<const u64t*>(&v1);
    }
#pragma unroll
    for (int i = 0; i < 4; ++i)
#pragma unroll
      for (int p = 0; p < P; ++p) {
        acc[i][p] = ffma2(a0[i], y0[p], acc[i][p]);
        acc[i][p] = ffma2(a1[i], y1[p], acc[i][p]);
      }
  }
}

// ---------------- Phase 1: per-chunk joint recurrence ------------------------
// Y (64x128): cols 0..63 = Xloc, 64..127 = Ploc. Dynamic smem: AsD + Ys.
__global__ __launch_bounds__(512) void k_phase1(const float* __restrict__ inp,
                                                const float* __restrict__ A,
                                                const float* __restrict__ Bst) {
  extern __shared__ float smem[];
  float* AsD = smem;                 // 8448 floats
  float* Ys  = smem + ASD_FLOATS;    // 8192 floats
  const int c = blockIdx.x, tid = threadIdx.x;
  const int cg = tid & 31, rg = tid >> 5;
  const int r0 = rg * 4, c0 = cg * 4;
  const int arow = tid >> 3, ak8 = (tid & 7) * 8;

  for (int i = tid; i < 64 * 128; i += 512) {
    int row = i >> 7, col = i & 127;
    Ys[i] = (col == row + 64) ? 1.0f : 0.0f;
  }

  const int t0 = c * LC;
  const float* Ap = A + (size_t)t0 * 4096;
  float4 cA0 = *reinterpret_cast<const float4*>(Ap + tid * 8);
  float4 cA1 = *reinterpret_cast<const float4*>(Ap + tid * 8 + 4);
  float4 bsv = *reinterpret_cast<const float4*>(Bst + t0 * 64 + r0);
  float4 inv = make_float4(0.f, 0.f, 0.f, 0.f);
  if (cg < 16) inv = *reinterpret_cast<const float4*>(inp + t0 * 64 + c0);
  store_dup8(AsD, arow, ak8, cA0, cA1);
  __syncthreads();

  for (int s = 0; s < LC; ++s) {
    const int t = t0 + s;
    float4 nA0, nA1, nbs, ninv;
    if (s + 1 < LC) {
      const float* Ap2 = A + (size_t)(t + 1) * 4096;
      nA0 = *reinterpret_cast<const float4*>(Ap2 + tid * 8);
      nA1 = *reinterpret_cast<const float4*>(Ap2 + tid * 8 + 4);
      nbs = *reinterpret_cast<const float4*>(Bst + (t + 1) * 64 + r0);
      ninv = make_float4(0.f, 0.f, 0.f, 0.f);
      if (cg < 16) ninv = *reinterpret_cast<const float4*>(inp + (t + 1) * 64 + c0);
    }

    u64t acc[4][2];
    if (cg < 16) {
      u64t ip0 = reinterpret_cast<const u64t*>(&inv)[0];
      u64t ip1 = reinterpret_cast<const u64t*>(&inv)[1];
      float bs[4] = {bsv.x, bsv.y, bsv.z, bsv.w};
#pragma unroll
      for (int i = 0; i < 4; ++i) {
        u64t bd = fdup(bs[i]);
        acc[i][0] = fmul2(bd, ip0);
        acc[i][1] = fmul2(bd, ip1);
      }
    } else {
#pragma unroll
      for (int i = 0; i < 4; ++i) { acc[i][0] = 0ull; acc[i][1] = 0ull; }
    }

    gemmP<128, 2>(AsD, Ys, acc, r0, c0);
    __syncthreads();

    if (s + 1 < LC) {
      store_dup8(AsD, arow, ak8, nA0, nA1);
      bsv = nbs; inv = ninv;
    }
#pragma unroll
    for (int i = 0; i < 4; ++i) {
      float4 v;
      reinterpret_cast<u64t*>(&v)[0] = acc[i][0];
      reinterpret_cast<u64t*>(&v)[1] = acc[i][1];
      *reinterpret_cast<float4*>(&Ys[(r0 + i) * 128 + c0]) = v;
      *reinterpret_cast<float4*>(&g_Y[((size_t)t * 64 + r0 + i) * 128 + c0]) = v;
    }
    __syncthreads();
  }
}

// ---------------- Scan init: gather chunk-final Y into g_S -------------------
__global__ __launch_bounds__(512) void k_scan_init() {
  const int c = blockIdx.x, tid = threadIdx.x;
  const size_t src = ((size_t)(c * LC + LC - 1)) * 64 * 128;
  const size_t dst = (size_t)c * 64 * 128;
#pragma unroll
  for (int i = 0; i < 4; ++i) {
    int idx = (tid + i * 512) * 4;
    *reinterpret_cast<float4*>(&g_S[dst + idx]) =
        *reinterpret_cast<const float4*>(&g_Y[src + idx]);
  }
}

// ---------------- Scan level (col-split 4x, packed) --------------------------
// CTA = (chunk c, colblock q of 32 cols). 256 threads: 4 rows x 2 cols each.
__global__ __launch_bounds__(256) void k_scan_level(int d, int pp) {
  const float* src = pp ? g_S2 : g_S;
  float*       dst = pp ? g_S  : g_S2;
  const int c = blockIdx.x >> 2, q = blockIdx.x & 3;
  const int tid = threadIdx.x;
  const size_t base = (size_t)c * 64 * 128;

  if (c < d) {  // copy through this col slice
    const int row = tid >> 2, col0 = q * 32 + (tid & 3) * 8;
#pragma unroll
    for (int i = 0; i < 2; ++i)
      *reinterpret_cast<float4*>(&dst[base + (size_t)row * 128 + col0 + i * 4]) =
          *reinterpret_cast<const float4*>(&src[base + (size_t)row * 128 + col0 + i * 4]);
    return;
  }

  __shared__ float AsD[ASD_FLOATS];   // dup P_c
  __shared__ float Ys32[64 * 32];     // col slice of Y_{c-d}
  const size_t prev = (size_t)(c - d) * 64 * 128;
  const int rg = tid >> 4, cgl = tid & 15;
  const int r0 = rg * 4, c0 = cgl * 2;
  const int gc0 = q * 32 + c0;

  {
    const int row = tid >> 2, k16 = (tid & 3) * 16;
    const float* p = &src[base + (size_t)row * 128 + 64 + k16];
    float4 f0 = *reinterpret_cast<const float4*>(p);
    float4 f1 = *reinterpret_cast<const float4*>(p + 4);
    float4 f2 = *reinterpret_cast<const float4*>(p + 8);
    float4 f3 = *reinterpret_cast<const float4*>(p + 12);
    store_dup8(AsD, row, k16, f0, f1);
    store_dup8(AsD, row, k16 + 8, f2, f3);
  }
  {
    const int row = tid >> 2, col = (tid & 3) * 8;
#pragma unroll
    for (int i = 0; i < 2; ++i)
      *reinterpret_cast<float4*>(&Ys32[row * 32 + col + i * 4]) =
          *reinterpret_cast<const float4*>(&src[prev + (size_t)row * 128 + q * 32 + col + i * 4]);
  }
  __syncthreads();

  u64t acc[4][1];
#pragma unroll
  for (int i = 0; i < 4; ++i) {
    if (q < 2) {  // E columns: add E_c
      float2 e = *reinterpret_cast<const float2*>(&src[base + (size_t)(r0 + i) * 128 + gc0]);
      acc[i][0] = *reinterpret_cast<const u64t*>(&e);
    } else {
      acc[i][0] = 0ull;
    }
  }
  gemmP<32, 1>(AsD, Ys32, acc, r0, c0);
#pragma unroll
  for (int i = 0; i < 4; ++i)
    *reinterpret_cast<float2*>(&dst[base + (size_t)(r0 + i) * 128 + gc0]) =
        *reinterpret_cast<const float2*>(&acc[i][0]);
}

// ---------------- Fixup: out[t] = Xloc[t] + Ploc[t] @ carry[c-1] -------------
// out layout (L,B,N): out[t*4096 + b*64 + n]. Dynamic smem: AsD + Ys(64x64).
__global__ __launch_bounds__(512) void k_fixup(float* __restrict__ out) {
  extern __shared__ float smem[];
  float* AsD = smem;                 // dup Ploc[t]
  float* Ys  = smem + ASD_FLOATS;    // carry (N x B), 4096 floats
  const int t = blockIdx.x, tid = threadIdx.x;
  const int c = t >> 5;
  const int cg = tid & 31, rg = tid >> 5;
  const int r0 = rg * 4, c0 = cg * 2;
  const size_t yb = (size_t)t * 64 * 128;

  u64t acc[4][1];
#pragma unroll
  for (int i = 0; i < 4; ++i) {
    float2 x = *reinterpret_cast<const float2*>(&g_Y[yb + (size_t)(r0 + i) * 128 + c0]);
    acc[i][0] = *reinterpret_cast<const u64t*>(&x);
  }

  if (c > 0) {
    const size_t sb = (size_t)(c - 1) * 64 * 128;  // inclusive scan (g_S2)
    {
      const int row = tid >> 3, k8 = (tid & 7) * 8;
      const float* p = &g_Y[yb + (size_t)row * 128 + 64 + k8];
      float4 f0 = *reinterpret_cast<const float4*>(p);
      float4 f1 = *reinterpret_cast<const float4*>(p + 4);
      store_dup8(AsD, row, k8, f0, f1);
    }
    {
      const int row = tid >> 3, col = (tid & 7) * 8;
#pragma unroll
      for (int i = 0; i < 2; ++i)
        *reinterpret_cast<float4*>(&Ys[row * 64 + col + i * 4]) =
            *reinterpret_cast<const float4*>(&g_S2[sb + (size_t)row * 128 + col + i * 4]);
    }
    __syncthreads();
    gemmP<64, 1>(AsD, Ys, acc, r0, c0);
  }

  // transposed store: acc[i][0] = (x[r0+i][c0], x[r0+i][c0+1]) -> out[t][b][n]
#pragma unroll
  for (int j = 0; j < 2; ++j) {
    float4 v;
    v.x = reinterpret_cast<const float2*>(&acc[0][0])[0].x,
    v.x = (j == 0) ? reinterpret_cast<const float2*>(&acc[0][0])->x
                   : reinterpret_cast<const float2*>(&acc[0][0])->y;
    v.y = (j == 0) ? reinterpret_cast<const float2*>(&acc[1][0])->x
                   : reinterpret_cast<const float2*>(&acc[1][0])->y;
    v.z = (j == 0) ? reinterpret_cast<const float2*>(&acc[2][0])->x
                   : reinterpret_cast<const float2*>(&acc[2][0])->y;
    v.w = (j == 0) ? reinterpret_cast<const float2*>(&acc[3][0])->x
                   : reinterpret_cast<const float2*>(&acc[3][0])->y;
    *reinterpret_cast<float4*>(&out[(size_t)t * 4096 + (size_t)(c0 + j) * 64 + r0]) = v;
  }
}

extern "C" void kernel_launch(void* const* d_in, const int* in_sizes, int n_in,
                              void* d_out, int out_size) {
  const float* inp = (const float*)d_in[0];   // (L, B)
  const float* A   = (const float*)d_in[1];   // (L, N, N)
  const float* Bst = (const float*)d_in[2];   // (L, N)
  float* out = (float*)d_out;

  const int p1_smem = (ASD_FLOATS + 64 * 128) * 4;   // 66560 B
  const int fx_smem = (ASD_FLOATS + 64 * 64) * 4;    // 50176 B
  static int attr_done = 0;
  cudaFuncSetAttribute(k_phase1, cudaFuncAttributeMaxDynamicSharedMemorySize, p1_smem);
  cudaFuncSetAttribute(k_fixup,  cudaFuncAttributeMaxDynamicSharedMemorySize, fx_smem);
  (void)attr_done;

  k_phase1<<<NCHUNK, 512, p1_smem>>>(inp, A, Bst);
  k_scan_init<<<NCHUNK, 512>>>();
  int pp = 0;
  for (int d = 1; d < NCHUNK; d <<= 1) {      // 7 levels; final result in g_S2
    k_scan_level<<<NCHUNK * 4, 256>>>(d, pp);
    pp ^= 1;
  }
  k_fixup<<<LTOT, 512, fx_smem>>>(out);
}

// round 16
// speedup vs baseline: 1.0016x; 1.0016x over previous
#include <cuda_runtime.h>

#define LTOT   4096
#define NST    64
#define BSZ    64
#define NCHUNK 128
#define LC     32

typedef unsigned long long u64t;

// Scratch (__device__ globals — no allocation allowed).
// g_Y[t][row n][col]: col 0..63 = Xloc (batch cols), col 64..127 = Ploc.
__device__ float g_Y [LTOT * 64 * 128];     // 128 MB
__device__ float g_S [NCHUNK * 64 * 128];
__device__ float g_S2[NCHUNK * 64 * 128];

// ---------------- packed f32x2 helpers --------------------------------------
__device__ __forceinline__ u64t ffma2(u64t a, u64t b, u64t c) {
  u64t d;
  asm("fma.rn.f32x2 %0, %1, %2, %3;" : "=l"(d) : "l"(a), "l"(b), "l"(c));
  return d;
}
__device__ __forceinline__ u64t fmul2(u64t a, u64t b) {
  u64t d;
  asm("mul.rn.f32x2 %0, %1, %2;" : "=l"(d) : "l"(a), "l"(b));
  return d;
}
__device__ __forceinline__ u64t fdup(float v) {
  u64t d; unsigned r = __float_as_uint(v);
  asm("mov.b64 %0, {%1, %1};" : "=l"(d) : "r"(r));
  return d;
}

// AsD: duplicated-A SMEM, float2 (a,a) per entry, row stride 66 entries.
#define ASD_FLOATS (64 * 66 * 2)   // 8448 floats = 33792 B

// Store 8 consecutive k-values of one A row, duplicated.
__device__ __forceinline__ void store_dup8(float* AsD, int row, int k8,
                                           float4 a, float4 b) {
  float* p = &AsD[(row * 66 + k8) * 2];
  *reinterpret_cast<float4*>(p)      = make_float4(a.x, a.x, a.y, a.y);
  *reinterpret_cast<float4*>(p + 4)  = make_float4(a.z, a.z, a.w, a.w);
  *reinterpret_cast<float4*>(p + 8)  = make_float4(b.x, b.x, b.y, b.y);
  *reinterpret_cast<float4*>(p + 12) = make_float4(b.z, b.z, b.w, b.w);
}

// Packed GEMM fragment: acc[4][P] (f32x2), rows r0..r0+3, col pairs at c0.
// W = Ys row stride in floats. AsD holds duplicated A.
template<int W, int P>
__device__ __forceinline__ void gemmP(const float* __restrict__ AsD,
                                      const float* __restrict__ Ys,
                                      u64t acc[4][P], int r0, int c0) {
#pragma unroll 8
  for (int k = 0; k < 64; k += 2) {
    u64t a0[4], a1[4];
#pragma unroll
    for (int i = 0; i < 4; ++i) {
      float4 av = *reinterpret_cast<const float4*>(&AsD[((r0 + i) * 66 + k) * 2]);
      a0[i] = reinterpret_cast<const u64t*>(&av)[0];
      a1[i] = reinterpret_cast<const u64t*>(&av)[1];
    }
    u64t y0[P], y1[P];
    if constexpr (P == 2) {
      float4 v0 = *reinterpret_cast<const float4*>(&Ys[k * W + c0]);
      float4 v1 = *reinterpret_cast<const float4*>(&Ys[(k + 1) * W + c0]);
      y0[0] = reinterpret_cast<const u64t*>(&v0)[0];
      y0[1] = reinterpret_cast<const u64t*>(&v0)[1];
      y1[0] = reinterpret_cast<const u64t*>(&v1)[0];
      y1[1] = reinterpret_cast<const u64t*>(&v1)[1];
    } else {
      float2 v0 = *reinterpret_cast<const float2*>(&Ys[k * W + c0]);
      float2 v1 = *reinterpret_cast<const float2*>(&Ys[(k + 1) * W + c0]);
      y0[0] = *reinterpret_cast<const u64t*>(&v0);
      y1[0] = *reinterpret_cast<const u64t*>(&v1);
    }
#pragma unroll
    for (int i = 0; i < 4; ++i)
#pragma unroll
      for (int p = 0; p < P; ++p) {
        acc[i][p] = ffma2(a0[i], y0[p], acc[i][p]);
        acc[i][p] = ffma2(a1[i], y1[p], acc[i][p]);
      }
  }
}

// ---------------- Phase 1: per-chunk joint recurrence ------------------------
// Y (64x128): cols 0..63 = Xloc, 64..127 = Ploc. Dynamic smem: AsD + Ys.
__global__ __launch_bounds__(512) void k_phase1(const float* __restrict__ inp,
                                                const float* __restrict__ A,
                                                const float* __restrict__ Bst) {
  extern __shared__ float smem[];
  float* AsD = smem;                 // 8448 floats
  float* Ys  = smem + ASD_FLOATS;    // 8192 floats
  const int c = blockIdx.x, tid = threadIdx.x;
  const int cg = tid & 31, rg = tid >> 5;
  const int r0 = rg * 4, c0 = cg * 4;
  const int arow = tid >> 3, ak8 = (tid & 7) * 8;

  for (int i = tid; i < 64 * 128; i += 512) {
    int row = i >> 7, col = i & 127;
    Ys[i] = (col == row + 64) ? 1.0f : 0.0f;
  }

  const int t0 = c * LC;
  const float* Ap = A + (size_t)t0 * 4096;
  float4 cA0 = *reinterpret_cast<const float4*>(Ap + tid * 8);
  float4 cA1 = *reinterpret_cast<const float4*>(Ap + tid * 8 + 4);
  float4 bsv = *reinterpret_cast<const float4*>(Bst + t0 * 64 + r0);
  float4 inv = make_float4(0.f, 0.f, 0.f, 0.f);
  if (cg < 16) inv = *reinterpret_cast<const float4*>(inp + t0 * 64 + c0);
  store_dup8(AsD, arow, ak8, cA0, cA1);
  __syncthreads();

  for (int s = 0; s < LC; ++s) {
    const int t = t0 + s;
    float4 nA0, nA1, nbs, ninv;
    if (s + 1 < LC) {
      const float* Ap2 = A + (size_t)(t + 1) * 4096;
      nA0 = *reinterpret_cast<const float4*>(Ap2 + tid * 8);
      nA1 = *reinterpret_cast<const float4*>(Ap2 + tid * 8 + 4);
      nbs = *reinterpret_cast<const float4*>(Bst + (t + 1) * 64 + r0);
      ninv = make_float4(0.f, 0.f, 0.f, 0.f);
      if (cg < 16) ninv = *reinterpret_cast<const float4*>(inp + (t + 1) * 64 + c0);
    }

    u64t acc[4][2];
    if (cg < 16) {
      u64t ip0 = reinterpret_cast<const u64t*>(&inv)[0];
      u64t ip1 = reinterpret_cast<const u64t*>(&inv)[1];
      float bs[4] = {bsv.x, bsv.y, bsv.z, bsv.w};
#pragma unroll
      for (int i = 0; i < 4; ++i) {
        u64t bd = fdup(bs[i]);
        acc[i][0] = fmul2(bd, ip0);
        acc[i][1] = fmul2(bd, ip1);
      }
    } else {
#pragma unroll
      for (int i = 0; i < 4; ++i) { acc[i][0] = 0ull; acc[i][1] = 0ull; }
    }

    gemmP<128, 2>(AsD, Ys, acc, r0, c0);
    __syncthreads();

    if (s + 1 < LC) {
      store_dup8(AsD, arow, ak8, nA0, nA1);
      bsv = nbs; inv = ninv;
    }
#pragma unroll
    for (int i = 0; i < 4; ++i) {
      float4 v;
      reinterpret_cast<u64t*>(&v)[0] = acc[i][0];
      reinterpret_cast<u64t*>(&v)[1] = acc[i][1];
      *reinterpret_cast<float4*>(&Ys[(r0 + i) * 128 + c0]) = v;
      *reinterpret_cast<float4*>(&g_Y[((size_t)t * 64 + r0 + i) * 128 + c0]) = v;
    }
    __syncthreads();
  }
}

// ---------------- Scan init: gather chunk-final Y into g_S -------------------
__global__ __launch_bounds__(512) void k_scan_init() {
  const int c = blockIdx.x, tid = threadIdx.x;
  const size_t src = ((size_t)(c * LC + LC - 1)) * 64 * 128;
  const size_t dst = (size_t)c * 64 * 128;
#pragma unroll
  for (int i = 0; i < 4; ++i) {
    int idx = (tid + i * 512) * 4;
    *reinterpret_cast<float4*>(&g_S[dst + idx]) =
        *reinterpret_cast<const float4*>(&g_Y[src + idx]);
  }
}

// ---------------- Scan level (col-split 4x, packed) --------------------------
// CTA = (chunk c, colblock q of 32 cols). 256 threads: 4 rows x 2 cols each.
__global__ __launch_bounds__(256) void k_scan_level(int d, int pp) {
  const float* src = pp ? g_S2 : g_S;
  float*       dst = pp ? g_S  : g_S2;
  const int c = blockIdx.x >> 2, q = blockIdx.x & 3;
  const int tid = threadIdx.x;
  const size_t base = (size_t)c * 64 * 128;

  if (c < d) {  // copy through this col slice
    const int row = tid >> 2, col0 = q * 32 + (tid & 3) * 8;
#pragma unroll
    for (int i = 0; i < 2; ++i)
      *reinterpret_cast<float4*>(&dst[base + (size_t)row * 128 + col0 + i * 4]) =
          *reinterpret_cast<const float4*>(&src[base + (size_t)row * 128 + col0 + i * 4]);
    return;
  }

  __shared__ float AsD[ASD_FLOATS];   // dup P_c
  __shared__ float Ys32[64 * 32];     // col slice of Y_{c-d}
  const size_t prev = (size_t)(c - d) * 64 * 128;
  const int rg = tid >> 4, cgl = tid & 15;
  const int r0 = rg * 4, c0 = cgl * 2;
  const int gc0 = q * 32 + c0;

  {
    const int row = tid >> 2, k16 = (tid & 3) * 16;
    const float* p = &src[base + (size_t)row * 128 + 64 + k16];
    float4 f0 = *reinterpret_cast<const float4*>(p);
    float4 f1 = *reinterpret_cast<const float4*>(p + 4);
    float4 f2 = *reinterpret_cast<const float4*>(p + 8);
    float4 f3 = *reinterpret_cast<const float4*>(p + 12);
    store_dup8(AsD, row, k16, f0, f1);
    store_dup8(AsD, row, k16 + 8, f2, f3);
  }
  {
    const int row = tid >> 2, col = (tid & 3) * 8;
#pragma unroll
    for (int i = 0; i < 2; ++i)
      *reinterpret_cast<float4*>(&Ys32[row * 32 + col + i * 4]) =
          *reinterpret_cast<const float4*>(&src[prev + (size_t)row * 128 + q * 32 + col + i * 4]);
  }
  __syncthreads();

  u64t acc[4][1];
#pragma unroll
  for (int i = 0; i < 4; ++i) {
    if (q < 2) {  // E columns: add E_c
      float2 e = *reinterpret_cast<const float2*>(&src[base + (size_t)(r0 + i) * 128 + gc0]);
      acc[i][0] = *reinterpret_cast<const u64t*>(&e);
    } else {
      acc[i][0] = 0ull;
    }
  }
  gemmP<32, 1>(AsD, Ys32, acc, r0, c0);
#pragma unroll
  for (int i = 0; i < 4; ++i)
    *reinterpret_cast<float2*>(&dst[base + (size_t)(r0 + i) * 128 + gc0]) =
        *reinterpret_cast<const float2*>(&acc[i][0]);
}

// ---------------- Fixup: out[t] = Xloc[t] + Ploc[t] @ carry[c-1] -------------
// out layout (L,B,N): out[t*4096 + b*64 + n]. Dynamic smem: AsD + Ys(64x64).
__global__ __launch_bounds__(512) void k_fixup(float* __restrict__ out) {
  extern __shared__ float smem[];
  float* AsD = smem;                 // dup Ploc[t]
  float* Ys  = smem + ASD_FLOATS;    // carry (N x B), 4096 floats
  const int t = blockIdx.x, tid = threadIdx.x;
  const int c = t >> 5;
  const int cg = tid & 31, rg = tid >> 5;
  const int r0 = rg * 4, c0 = cg * 2;
  const size_t yb = (size_t)t * 64 * 128;

  u64t acc[4][1];
#pragma unroll
  for (int i = 0; i < 4; ++i) {
    float2 x = *reinterpret_cast<const float2*>(&g_Y[yb + (size_t)(r0 + i) * 128 + c0]);
    acc[i][0] = *reinterpret_cast<const u64t*>(&x);
  }

  if (c > 0) {
    const size_t sb = (size_t)(c - 1) * 64 * 128;  // inclusive scan (g_S2)
    {
      const int row = tid >> 3, k8 = (tid & 7) * 8;
      const float* p = &g_Y[yb + (size_t)row * 128 + 64 + k8];
      float4 f0 = *reinterpret_cast<const float4*>(p);
      float4 f1 = *reinterpret_cast<const float4*>(p + 4);
      store_dup8(AsD, row, k8, f0, f1);
    }
    {
      const int row = tid >> 3, col = (tid & 7) * 8;
#pragma unroll
      for (int i = 0; i < 2; ++i)
        *reinterpret_cast<float4*>(&Ys[row * 64 + col + i * 4]) =
            *reinterpret_cast<const float4*>(&g_S2[sb + (size_t)row * 128 + col + i * 4]);
    }
    __syncthreads();
    gemmP<64, 1>(AsD, Ys, acc, r0, c0);
  }

  // transposed store: acc[i][0] = (x[r0+i][c0], x[r0+i][c0+1]) -> out[t][b][n]
#pragma unroll
  for (int j = 0; j < 2; ++j) {
    float4 v;
    v.x = reinterpret_cast<const float2*>(&acc[0][0])[0].x,
    v.x = (j == 0) ? reinterpret_cast<const float2*>(&acc[0][0])->x
                   : reinterpret_cast<const float2*>(&acc[0][0])->y;
    v.y = (j == 0) ? reinterpret_cast<const float2*>(&acc[1][0])->x
                   : reinterpret_cast<const float2*>(&acc[1][0])->y;
    v.z = (j == 0) ? reinterpret_cast<const float2*>(&acc[2][0])->x
                   : reinterpret_cast<const float2*>(&acc[2][0])->y;
    v.w = (j == 0) ? reinterpret_cast<const float2*>(&acc[3][0])->x
                   : reinterpret_cast<const float2*>(&acc[3][0])->y;
    *reinterpret_cast<float4*>(&out[(size_t)t * 4096 + (size_t)(c0 + j) * 64 + r0]) = v;
  }
}

extern "C" void kernel_launch(void* const* d_in, const int* in_sizes, int n_in,
                              void* d_out, int out_size) {
  const float* inp = (const float*)d_in[0];   // (L, B)
  const float* A   = (const float*)d_in[1];   // (L, N, N)
  const float* Bst = (const float*)d_in[2];   // (L, N)
  float* out = (float*)d_out;

  const int p1_smem = (ASD_FLOATS + 64 * 128) * 4;   // 66560 B
  const int fx_smem = (ASD_FLOATS + 64 * 64) * 4;    // 50176 B
  static int attr_done = 0;
  cudaFuncSetAttribute(k_phase1, cudaFuncAttributeMaxDynamicSharedMemorySize, p1_smem);
  cudaFuncSetAttribute(k_fixup,  cudaFuncAttributeMaxDynamicSharedMemorySize, fx_smem);
  (void)attr_done;

  k_phase1<<<NCHUNK, 512, p1_smem>>>(inp, A, Bst);
  k_scan_init<<<NCHUNK, 512>>>();
  int pp = 0;
  for (int d = 1; d < NCHUNK; d <<= 1) {      // 7 levels; final result in g_S2
    k_scan_level<<<NCHUNK * 4, 256>>>(d, pp);
    pp ^= 1;
  }
  k_fixup<<<LTOT, 512, fx_smem>>>(out);
}